// round 2
// baseline (speedup 1.0000x reference)
#include <cuda_runtime.h>
#include <math.h>

#define BATCH  1024
#define TSTEPS 1024
#define DIN    6
#define UNITS  64
#define WIDTH  128
#define DOUT   6
#define K0     70          // DIN + UNITS
#define EPSF   1e-8f
#define ROWS   8
#define NTH    256
#define NBLK   (BATCH / ROWS)

// ---------------- shared memory layout (float offsets) ----------------
#define SW0A   0                      // 128 cols * stride 71  (K=70)
#define SW0B   (SW0A + 128 * 71)      // 9088
#define SW1A   (SW0B + 128 * 71)      // 18176, 128 cols * stride 129
#define SW1B   (SW1A + 128 * 129)     // 34688
#define BOFF   (SW1B + 128 * 129)     // 51200: b10,b20,b11,b21,b12,b22 (6*128)
#define BA_OFF (BOFF + 6 * 128)       // 51968 (64)
#define BB_OFF (BA_OFF + 64)          // 52032 (64)
#define WO_OFF (BB_OFF + 64)          // 52096 (64*6 = 384)
#define C0     (WO_OFF + 384)         // 52480: 8 rows * stride 72 : [xn(6)|h(64)]
#define CBUF   (C0 + 8 * 72)          // 53056: 8 * 128
#define STG    (CBUF + 8 * 128)       // 54080: 2 * 8 * 128 staging (aliased as head partials)
#define XB     (STG + 2048)           // 56128: 8 * 6
#define NB     (XB + 48)              // 56176: 8 norms
#define SMEM_FLOATS (NB + 8)          // 56184 -> 224736 bytes

// y[8 rows] = c[8][CS] @ w_col(smem scalar) + bias, K deep
template<int K, int CS>
__device__ __forceinline__ void mv8s(float (&v)[8], const float* __restrict__ cb,
                                     const float* __restrict__ wp, float bias)
{
    constexpr int KV = K & ~3;
#pragma unroll
    for (int rg = 0; rg < 2; rg++) {
        const float* c = cb + rg * 4 * CS;
        float a0 = bias, a1 = bias, a2 = bias, a3 = bias;
#pragma unroll 4
        for (int k = 0; k < KV; k += 4) {
            const float w0 = wp[k], w1 = wp[k + 1], w2 = wp[k + 2], w3 = wp[k + 3];
            const float4 q0 = *(const float4*)(c + k);
            const float4 q1 = *(const float4*)(c + CS + k);
            const float4 q2 = *(const float4*)(c + 2 * CS + k);
            const float4 q3 = *(const float4*)(c + 3 * CS + k);
            a0 = fmaf(q0.x, w0, a0); a0 = fmaf(q0.y, w1, a0); a0 = fmaf(q0.z, w2, a0); a0 = fmaf(q0.w, w3, a0);
            a1 = fmaf(q1.x, w0, a1); a1 = fmaf(q1.y, w1, a1); a1 = fmaf(q1.z, w2, a1); a1 = fmaf(q1.w, w3, a1);
            a2 = fmaf(q2.x, w0, a2); a2 = fmaf(q2.y, w1, a2); a2 = fmaf(q2.z, w2, a2); a2 = fmaf(q2.w, w3, a2);
            a3 = fmaf(q3.x, w0, a3); a3 = fmaf(q3.y, w1, a3); a3 = fmaf(q3.z, w2, a3); a3 = fmaf(q3.w, w3, a3);
        }
#pragma unroll
        for (int k = KV; k < K; k++) {
            const float w = wp[k];
            a0 = fmaf(c[k], w, a0);
            a1 = fmaf(c[CS + k], w, a1);
            a2 = fmaf(c[2 * CS + k], w, a2);
            a3 = fmaf(c[3 * CS + k], w, a3);
        }
        v[rg * 4 + 0] = a0; v[rg * 4 + 1] = a1; v[rg * 4 + 2] = a2; v[rg * 4 + 3] = a3;
    }
}

// y[8 rows] = c[8][CS] @ w_col(register-resident) + bias; K multiple of 4, fully unrolled
template<int K, int CS>
__device__ __forceinline__ void mv8r(float (&v)[8], const float* __restrict__ cb,
                                     const float (&wr)[K], float bias)
{
#pragma unroll
    for (int rg = 0; rg < 2; rg++) {
        const float* c = cb + rg * 4 * CS;
        float a0 = bias, a1 = bias, a2 = bias, a3 = bias;
#pragma unroll
        for (int k = 0; k < K; k += 4) {
            const float4 q0 = *(const float4*)(c + k);
            const float4 q1 = *(const float4*)(c + CS + k);
            const float4 q2 = *(const float4*)(c + 2 * CS + k);
            const float4 q3 = *(const float4*)(c + 3 * CS + k);
            a0 = fmaf(q0.x, wr[k], a0); a0 = fmaf(q0.y, wr[k+1], a0); a0 = fmaf(q0.z, wr[k+2], a0); a0 = fmaf(q0.w, wr[k+3], a0);
            a1 = fmaf(q1.x, wr[k], a1); a1 = fmaf(q1.y, wr[k+1], a1); a1 = fmaf(q1.z, wr[k+2], a1); a1 = fmaf(q1.w, wr[k+3], a1);
            a2 = fmaf(q2.x, wr[k], a2); a2 = fmaf(q2.y, wr[k+1], a2); a2 = fmaf(q2.z, wr[k+2], a2); a2 = fmaf(q2.w, wr[k+3], a2);
            a3 = fmaf(q3.x, wr[k], a3); a3 = fmaf(q3.y, wr[k+1], a3); a3 = fmaf(q3.z, wr[k+2], a3); a3 = fmaf(q3.w, wr[k+3], a3);
        }
        v[rg * 4 + 0] = a0; v[rg * 4 + 1] = a1; v[rg * 4 + 2] = a2; v[rg * 4 + 3] = a3;
    }
}

__global__ void __launch_bounds__(NTH, 1)
lmsc_kernel(const float* __restrict__ x,   const float* __restrict__ initF,
            const float* __restrict__ w10, const float* __restrict__ b10,
            const float* __restrict__ w20, const float* __restrict__ b20,
            const float* __restrict__ w11, const float* __restrict__ b11,
            const float* __restrict__ w21, const float* __restrict__ b21,
            const float* __restrict__ w12, const float* __restrict__ b12,
            const float* __restrict__ w22, const float* __restrict__ b22,
            const float* __restrict__ wa,  const float* __restrict__ ba,
            const float* __restrict__ wb,  const float* __restrict__ bb,
            const float* __restrict__ wout, float* __restrict__ out)
{
    extern __shared__ float sm[];
    const int tid = threadIdx.x;
    const int b0  = blockIdx.x * ROWS;
    const int m   = tid >> 7;        // which matrix of the pair
    const int j   = tid & 127;       // output column

    // ---- load weights into SMEM (transposed, odd stride) ----
    for (int idx = tid; idx < K0 * WIDTH; idx += NTH) {
        int k = idx >> 7, jj = idx & 127;
        sm[SW0A + jj * 71 + k] = w10[idx];
        sm[SW0B + jj * 71 + k] = w20[idx];
    }
    for (int idx = tid; idx < WIDTH * WIDTH; idx += NTH) {
        int k = idx >> 7, jj = idx & 127;
        sm[SW1A + jj * 129 + k] = w11[idx];
        sm[SW1B + jj * 129 + k] = w21[idx];
    }
    if (tid < 128) {
        sm[BOFF +        tid] = b10[tid];
        sm[BOFF + 128  + tid] = b20[tid];
        sm[BOFF + 256  + tid] = b11[tid];
        sm[BOFF + 384  + tid] = b21[tid];
        sm[BOFF + 512  + tid] = b12[tid];
        sm[BOFF + 640  + tid] = b22[tid];
    }
    if (tid < 64) { sm[BA_OFF + tid] = ba[tid]; sm[BB_OFF + tid] = bb[tid]; }
    for (int idx = tid; idx < UNITS * DOUT; idx += NTH) sm[WO_OFF + idx] = wout[idx];
    // h0 = init_F[:, 2:66]
    for (int idx = tid; idx < ROWS * UNITS; idx += NTH) {
        int r = idx >> 6, jj = idx & 63;
        sm[C0 + r * 72 + 6 + jj] = initF[(b0 + r) * (2 + UNITS) + 2 + jj];
    }

    // ---- register-resident weights: layer 2 column + head slice ----
    float wl2[128];
    {
        const float* wsrc = m ? w22 : w12;
#pragma unroll
        for (int k = 0; k < 128; k++) wl2[k] = wsrc[k * 128 + j];
    }
    const float bias0 = (m ? b20 : b10)[j];
    const float bias1 = (m ? b21 : b11)[j];
    const float bias2 = (m ? b22 : b12)[j];

    const int hm = tid >> 7;          // 0 -> wa, 1 -> wb
    const int kh = (tid >> 6) & 1;    // which 64-deep half of K
    const int jh = tid & 63;          // head output column
    float whd[64];
    {
        const float* hsrc = hm ? wb : wa;
#pragma unroll
        for (int i = 0; i < 64; i++) whd[i] = hsrc[(kh * 64 + i) * 64 + jh];
    }

    // ---- x prefetch (t = 0) ----
    float xc = 0.f;
    const int xr = tid / 6, xd = tid - 6 * xr;
    if (tid < 48) xc = x[((size_t)(b0 + xr) * TSTEPS) * 6 + xd];

    float* outs = out;
    float* alph = out + (size_t)BATCH * TSTEPS * DOUT;

#pragma unroll 1
    for (int t = 0; t < TSTEPS; t++) {
        __syncthreads();                                  // S_A: stage/c0 free
        if (tid < 48) sm[XB + tid] = xc;
        __syncthreads();                                  // S_B: xbuf visible
        if (tid < 48 && t + 1 < TSTEPS)
            xc = x[((size_t)(b0 + xr) * TSTEPS + (t + 1)) * 6 + xd];  // prefetch next
        if (tid < 8) {
            float s = 0.f;
#pragma unroll
            for (int d = 0; d < 6; d++) { float v = sm[XB + tid * 6 + d]; s = fmaf(v, v, s); }
            float nrm = sqrtf(s);
            sm[NB + tid] = nrm;
            float inv = 1.0f / (nrm + EPSF);
#pragma unroll
            for (int d = 0; d < 6; d++) sm[C0 + tid * 72 + d] = sm[XB + tid * 6 + d] * inv;
        }
        __syncthreads();                                  // S_C: c0 ready

        {   // layer 0 (SMEM weights, K=70), tanh
            float v[8];
            mv8s<K0, 72>(v, sm + C0, sm + (m ? SW0B : SW0A) + j * 71, bias0);
#pragma unroll
            for (int r = 0; r < 8; r++) sm[STG + m * 1024 + r * 128 + j] = tanhf(v[r]);
        }
        __syncthreads();                                  // S_D
        for (int idx = tid; idx < 1024; idx += NTH)
            sm[CBUF + idx] = sm[STG + idx] * sm[STG + 1024 + idx];
        __syncthreads();                                  // S_E

        {   // layer 1 (SMEM weights, K=128), tanh
            float v[8];
            mv8s<128, 128>(v, sm + CBUF, sm + (m ? SW1B : SW1A) + j * 129, bias1);
#pragma unroll
            for (int r = 0; r < 8; r++) sm[STG + m * 1024 + r * 128 + j] = tanhf(v[r]);
        }
        __syncthreads();                                  // S_F
        for (int idx = tid; idx < 1024; idx += NTH)
            sm[CBUF + idx] = sm[STG + idx] * sm[STG + 1024 + idx];
        __syncthreads();                                  // S_G

        {   // layer 2 (register weights, K=128), no tanh before product
            float v[8];
            mv8r<128, 128>(v, sm + CBUF, wl2, bias2);
#pragma unroll
            for (int r = 0; r < 8; r++) sm[STG + m * 1024 + r * 128 + j] = v[r];
        }
        __syncthreads();                                  // S_H
        for (int idx = tid; idx < 1024; idx += NTH)
            sm[CBUF + idx] = tanhf(sm[STG + idx] * sm[STG + 1024 + idx]);   // g
        __syncthreads();                                  // S_I

        {   // heads: partial dot over this thread's 64-deep half (register weights)
            float p[8];
            mv8r<64, 128>(p, sm + CBUF + kh * 64, whd, 0.f);
#pragma unroll
            for (int r = 0; r < 8; r++)
                sm[STG + ((hm * 2 + kh) * 8 + r) * 64 + jh] = p[r];
        }
        __syncthreads();                                  // S_J

        {   // combine heads, state update, alpha out
            const int jj = tid & 63;
            const int r0 = (tid >> 6) * 2;
#pragma unroll
            for (int rr = 0; rr < 2; rr++) {
                const int r = r0 + rr;
                float pa = sm[STG + (0 * 8 + r) * 64 + jj] + sm[STG + (1 * 8 + r) * 64 + jj];
                float alpha = expf(pa + sm[BA_OFF + jj]);
                float pb = sm[STG + (2 * 8 + r) * 64 + jj] + sm[STG + (3 * 8 + r) * 64 + jj];
                float beta = tanhf(pb + sm[BB_OFF + jj]);
                float hold = sm[C0 + r * 72 + 6 + jj];
                float nrm  = sm[NB + r];
                float hn = fmaf(expf(-alpha * nrm), hold - beta, beta);
                sm[C0 + r * 72 + 6 + jj] = hn;
                alph[((size_t)(b0 + r) * TSTEPS + t) * 64 + jj] = alpha;
            }
        }
        __syncthreads();                                  // S_K: h_new visible

        if (tid < 48) {   // outs = h_new @ wout (64 -> 6)
            const int r = tid / 6, o = tid - 6 * r;
            float acc = 0.f;
#pragma unroll
            for (int k = 0; k < 64; k++)
                acc = fmaf(sm[C0 + r * 72 + 6 + k], sm[WO_OFF + k * 6 + o], acc);
            outs[((size_t)(b0 + r) * TSTEPS + t) * 6 + o] = acc;
        }
    }
}

extern "C" void kernel_launch(void* const* d_in, const int* in_sizes, int n_in,
                              void* d_out, int out_size)
{
    const float* x     = (const float*)d_in[0];
    const float* initF = (const float*)d_in[1];
    const float* w10   = (const float*)d_in[2];
    const float* b10   = (const float*)d_in[3];
    const float* w20   = (const float*)d_in[4];
    const float* b20   = (const float*)d_in[5];
    const float* w11   = (const float*)d_in[6];
    const float* b11   = (const float*)d_in[7];
    const float* w21   = (const float*)d_in[8];
    const float* b21   = (const float*)d_in[9];
    const float* w12   = (const float*)d_in[10];
    const float* b12   = (const float*)d_in[11];
    const float* w22   = (const float*)d_in[12];
    const float* b22   = (const float*)d_in[13];
    const float* wa    = (const float*)d_in[14];
    const float* ba    = (const float*)d_in[15];
    const float* wb    = (const float*)d_in[16];
    const float* bb    = (const float*)d_in[17];
    const float* wout  = (const float*)d_in[18];
    float* out = (float*)d_out;

    const int smem_bytes = SMEM_FLOATS * 4;
    cudaFuncSetAttribute(lmsc_kernel, cudaFuncAttributeMaxDynamicSharedMemorySize, smem_bytes);

    lmsc_kernel<<<NBLK, NTH, smem_bytes>>>(x, initF,
                                           w10, b10, w20, b20,
                                           w11, b11, w21, b21,
                                           w12, b12, w22, b22,
                                           wa, ba, wb, bb, wout, out);
}

// round 4
// speedup vs baseline: 1.0210x; 1.0210x over previous
#include <cuda_runtime.h>
#include <math.h>

typedef unsigned long long ull;

#define BATCH  1024
#define TSTEPS 1024
#define DIN    6
#define UNITS  64
#define WIDTH  128
#define DOUT   6
#define K0     70
#define EPSF   1e-8f
#define ROWS   8
#define NTH    256
#define NBLK   (BATCH / ROWS)

// ---------------- shared memory layout (float offsets) ----------------
// WI0: layer0 weight pair interleaved: col j at j*142, k at 2k -> (w10,w20)
// WI1: layer1 weight pair interleaved: col j at j*258
// C0P: layer0 input, dup-pair layout: k*16 + r*2 (+0/+1 duplicate), k<70
// CBD: layer0 gate output, dup-pair layout: k*16 + r*2, k<128
// CB2: layer1 gate / layer2 gate, rowpair layout: k*8 + p*2 + e  (row = 2p+e)
// STGO: layer2 x1/x2 exchange [m][p][j] pairs (2*1024)
//       ALSO head partials, compact: [g][p][jh] pairs, g*512 + p*128 + jh*2 + e (4*512 = 2048)
#define WI0   0
#define WI1   18176          // + 128*142
#define WOUT  51200          // + 128*258
#define BA    51584
#define BB    51648
#define C0P   51712          // 70*16 = 1120
#define CBD   52832          // 128*16 = 2048
#define CB2   54880          // 128*8 = 1024
#define STGO  55904          // 2048
#define XB    57952          // 48
#define NB    58000          // 8
#define SMF   58008          // 232,032 bytes <= 232,448 cap

__device__ __forceinline__ ull pack2(float lo, float hi) {
    ull r; asm("mov.b64 %0, {%1, %2};" : "=l"(r) : "f"(lo), "f"(hi)); return r;
}
__device__ __forceinline__ void unpack2(ull v, float& lo, float& hi) {
    asm("mov.b64 {%0, %1}, %2;" : "=f"(lo), "=f"(hi) : "l"(v));
}
__device__ __forceinline__ void ffma2(ull& d, ull a, ull b) {
    asm("fma.rn.f32x2 %0, %1, %2, %0;" : "+l"(d) : "l"(a), "l"(b));
}

// Fused both-mats layer: acc packs (mat1, mat2); acts dup-pair; weights interleaved.
// g[i] = tanh(x1)*tanh(x2) for the 4 rows this thread owns.
template<int K>
__device__ __forceinline__ void layer_fused(float (&g)[4], const float* __restrict__ actp,
                                            const float* __restrict__ wp, ull binit)
{
    ull a0 = binit, a1 = binit, a2 = binit, a3 = binit;
#pragma unroll 16
    for (int k = 0; k < K; k++) {
        ulonglong2 u0 = *(const ulonglong2*)(actp + k * 16);
        ulonglong2 u1 = *(const ulonglong2*)(actp + k * 16 + 4);
        ull w = *(const ull*)(wp + 2 * k);
        ffma2(a0, u0.x, w); ffma2(a1, u0.y, w);
        ffma2(a2, u1.x, w); ffma2(a3, u1.y, w);
    }
    float x1, x2;
    unpack2(a0, x1, x2); g[0] = tanhf(x1) * tanhf(x2);
    unpack2(a1, x1, x2); g[1] = tanhf(x1) * tanhf(x2);
    unpack2(a2, x1, x2); g[2] = tanhf(x1) * tanhf(x2);
    unpack2(a3, x1, x2); g[3] = tanhf(x1) * tanhf(x2);
}

__global__ void __launch_bounds__(NTH, 1)
lmsc_kernel(const float* __restrict__ x,   const float* __restrict__ initF,
            const float* __restrict__ w10, const float* __restrict__ b10,
            const float* __restrict__ w20, const float* __restrict__ b20,
            const float* __restrict__ w11, const float* __restrict__ b11,
            const float* __restrict__ w21, const float* __restrict__ b21,
            const float* __restrict__ w12, const float* __restrict__ b12,
            const float* __restrict__ w22, const float* __restrict__ b22,
            const float* __restrict__ wa,  const float* __restrict__ ba,
            const float* __restrict__ wb,  const float* __restrict__ bb,
            const float* __restrict__ wout, float* __restrict__ out)
{
    extern __shared__ float sm[];
    const int tid = threadIdx.x;
    const int b0  = blockIdx.x * ROWS;
    const int rh  = tid >> 7;        // row-half for fused layers; mat index for L2
    const int j   = tid & 127;       // column

    // ---- SMEM weight init ----
    for (int idx = tid; idx < K0 * WIDTH; idx += NTH) {
        int k = idx >> 7, jj = idx & 127;
        sm[WI0 + jj * 142 + 2 * k]     = w10[idx];
        sm[WI0 + jj * 142 + 2 * k + 1] = w20[idx];
    }
    for (int idx = tid; idx < WIDTH * WIDTH; idx += NTH) {
        int k = idx >> 7, jj = idx & 127;
        sm[WI1 + jj * 258 + 2 * k]     = w11[idx];
        sm[WI1 + jj * 258 + 2 * k + 1] = w21[idx];
    }
    for (int idx = tid; idx < UNITS * DOUT; idx += NTH) sm[WOUT + idx] = wout[idx];
    if (tid < 64) { sm[BA + tid] = ba[tid]; sm[BB + tid] = bb[tid]; }
    // h0 into dup-pair layout of C0P
    for (int idx = tid; idx < ROWS * UNITS; idx += NTH) {
        int r = idx >> 6, jj = idx & 63;
        float v = initF[(b0 + r) * (2 + UNITS) + 2 + jj];
        sm[C0P + (6 + jj) * 16 + r * 2]     = v;
        sm[C0P + (6 + jj) * 16 + r * 2 + 1] = v;
    }

    // ---- per-thread register state ----
    const ull bp0 = pack2(b10[j], b20[j]);
    const ull bp1 = pack2(b11[j], b21[j]);
    const float bias2 = (rh ? b22 : b12)[j];

    float wl2[128];
    {
        const float* wsrc = rh ? w22 : w12;
#pragma unroll
        for (int k = 0; k < 128; k++) wl2[k] = wsrc[k * 128 + j];
    }
    const int hm = tid >> 7;          // 0 -> wa, 1 -> wb
    const int kh = (tid >> 6) & 1;    // K half
    const int jh = tid & 63;
    float whd[64];
    {
        const float* hsrc = hm ? wb : wa;
#pragma unroll
        for (int i = 0; i < 64; i++) whd[i] = hsrc[(kh * 64 + i) * 64 + jh];
    }

    const float* actC0 = sm + C0P + rh * 8;
    const float* actCB = sm + CBD + rh * 8;
    const float* wp0   = sm + WI0 + j * 142;
    const float* wp1   = sm + WI1 + j * 258;

    // x prefetch
    float xc = 0.f;
    const int xr = tid / 6, xd = tid - 6 * xr;
    if (tid < 48) xc = x[((size_t)(b0 + xr) * TSTEPS) * 6 + xd];

    float* outs = out;
    float* alph = out + (size_t)BATCH * TSTEPS * DOUT;

#pragma unroll 1
    for (int t = 0; t < TSTEPS; t++) {
        __syncthreads();                                   // (1)
        if (tid < 48) sm[XB + tid] = xc;
        __syncthreads();                                   // (2)
        if (tid < 48 && t + 1 < TSTEPS)
            xc = x[((size_t)(b0 + xr) * TSTEPS + (t + 1)) * 6 + xd];
        if (tid < 8) {
            float s = 0.f;
#pragma unroll
            for (int d = 0; d < 6; d++) { float v = sm[XB + tid * 6 + d]; s = fmaf(v, v, s); }
            float nrm = sqrtf(s);
            sm[NB + tid] = nrm;
            float inv = 1.0f / (nrm + EPSF);
#pragma unroll
            for (int d = 0; d < 6; d++) {
                float v = sm[XB + tid * 6 + d] * inv;
                sm[C0P + d * 16 + tid * 2]     = v;
                sm[C0P + d * 16 + tid * 2 + 1] = v;
            }
        }
        __syncthreads();                                   // (3) c0 ready

        {   // layer 0 fused -> CBD (dup-pair)
            float g[4];
            layer_fused<K0>(g, actC0, wp0, bp0);
            float4 s0 = make_float4(g[0], g[0], g[1], g[1]);
            float4 s1 = make_float4(g[2], g[2], g[3], g[3]);
            *(float4*)(sm + CBD + j * 16 + rh * 8)     = s0;
            *(float4*)(sm + CBD + j * 16 + rh * 8 + 4) = s1;
        }
        __syncthreads();                                   // (4)

        {   // layer 1 fused -> CB2 (rowpair)
            float g[4];
            layer_fused<WIDTH>(g, actCB, wp1, bp1);
            *(float4*)(sm + CB2 + j * 8 + rh * 4) = make_float4(g[0], g[1], g[2], g[3]);
        }
        __syncthreads();                                   // (5)

        {   // layer 2: split-mat, reg weights, rowpair acts -> STGO (m*1024 + p*256 + j*2)
            ull bp = pack2(bias2, bias2);
            ull a0 = bp, a1 = bp, a2 = bp, a3 = bp;
#pragma unroll
            for (int k = 0; k < 128; k++) {
                ulonglong2 u0 = *(const ulonglong2*)(sm + CB2 + k * 8);
                ulonglong2 u1 = *(const ulonglong2*)(sm + CB2 + k * 8 + 4);
                ull w = pack2(wl2[k], wl2[k]);
                ffma2(a0, u0.x, w); ffma2(a1, u0.y, w);
                ffma2(a2, u1.x, w); ffma2(a3, u1.y, w);
            }
            *(ull*)(sm + STGO + rh * 1024 + 0 * 256 + j * 2) = a0;
            *(ull*)(sm + STGO + rh * 1024 + 1 * 256 + j * 2) = a1;
            *(ull*)(sm + STGO + rh * 1024 + 2 * 256 + j * 2) = a2;
            *(ull*)(sm + STGO + rh * 1024 + 3 * 256 + j * 2) = a3;
        }
        __syncthreads();                                   // (6)

        // gate pass: CB2[j'*8 + p*2 + e] = tanh(x1 * x2)
#pragma unroll
        for (int it = 0; it < 4; it++) {
            int idx = it * 256 + tid;                      // = j'*8 + p*2 + e
            int jq  = idx >> 3;
            int rem = idx & 7;                             // p*2 + e
            int src = ((rem >> 1) * 256) + jq * 2 + (rem & 1);
            float x1 = sm[STGO + src];
            float x2 = sm[STGO + 1024 + src];
            sm[CB2 + idx] = tanhf(x1 * x2);
        }
        __syncthreads();                                   // (7)

        {   // heads: split-K, reg weights -> compact partials g*512 + p*128 + jh*2 + e
            const float* actH = sm + CB2 + kh * 64 * 8;
            ull a0 = 0, a1 = 0, a2 = 0, a3 = 0;
#pragma unroll
            for (int i = 0; i < 64; i++) {
                ulonglong2 u0 = *(const ulonglong2*)(actH + i * 8);
                ulonglong2 u1 = *(const ulonglong2*)(actH + i * 8 + 4);
                ull w = pack2(whd[i], whd[i]);
                ffma2(a0, u0.x, w); ffma2(a1, u0.y, w);
                ffma2(a2, u1.x, w); ffma2(a3, u1.y, w);
            }
            const int g = hm * 2 + kh;
            *(ull*)(sm + STGO + g * 512 + 0 * 128 + jh * 2) = a0;
            *(ull*)(sm + STGO + g * 512 + 1 * 128 + jh * 2) = a1;
            *(ull*)(sm + STGO + g * 512 + 2 * 128 + jh * 2) = a2;
            *(ull*)(sm + STGO + g * 512 + 3 * 128 + jh * 2) = a3;
        }
        __syncthreads();                                   // (8)

        {   // combine: alpha/beta, h update, alpha out (2 rows per thread)
            const int jj = tid & 63;
            const int rg = tid >> 6;                       // pair index p
#pragma unroll
            for (int rr = 0; rr < 2; rr++) {
                const int r = rg * 2 + rr;
                float pa = sm[STGO + 0 * 512 + rg * 128 + jj * 2 + rr]
                         + sm[STGO + 1 * 512 + rg * 128 + jj * 2 + rr];
                float pb = sm[STGO + 2 * 512 + rg * 128 + jj * 2 + rr]
                         + sm[STGO + 3 * 512 + rg * 128 + jj * 2 + rr];
                float alpha = expf(pa + sm[BA + jj]);
                float beta  = tanhf(pb + sm[BB + jj]);
                float hold  = sm[C0P + (6 + jj) * 16 + r * 2];
                float hn = fmaf(expf(-alpha * sm[NB + r]), hold - beta, beta);
                sm[C0P + (6 + jj) * 16 + r * 2]     = hn;
                sm[C0P + (6 + jj) * 16 + r * 2 + 1] = hn;
                alph[((size_t)(b0 + r) * TSTEPS + t) * 64 + jj] = alpha;
            }
        }
        __syncthreads();                                   // (9)

        if (tid < 48) {   // outs = h_new @ wout
            const int r = tid / 6, o = tid - 6 * r;
            float acc = 0.f;
#pragma unroll
            for (int k = 0; k < 64; k++)
                acc = fmaf(sm[C0P + (6 + k) * 16 + r * 2], sm[WOUT + k * 6 + o], acc);
            outs[((size_t)(b0 + r) * TSTEPS + t) * 6 + o] = acc;
        }
    }
}

extern "C" void kernel_launch(void* const* d_in, const int* in_sizes, int n_in,
                              void* d_out, int out_size)
{
    const float* x     = (const float*)d_in[0];
    const float* initF = (const float*)d_in[1];
    const float* w10   = (const float*)d_in[2];
    const float* b10   = (const float*)d_in[3];
    const float* w20   = (const float*)d_in[4];
    const float* b20   = (const float*)d_in[5];
    const float* w11   = (const float*)d_in[6];
    const float* b11   = (const float*)d_in[7];
    const float* w21   = (const float*)d_in[8];
    const float* b21   = (const float*)d_in[9];
    const float* w12   = (const float*)d_in[10];
    const float* b12   = (const float*)d_in[11];
    const float* w22   = (const float*)d_in[12];
    const float* b22   = (const float*)d_in[13];
    const float* wa    = (const float*)d_in[14];
    const float* ba    = (const float*)d_in[15];
    const float* wb    = (const float*)d_in[16];
    const float* bb    = (const float*)d_in[17];
    const float* wout  = (const float*)d_in[18];
    float* out = (float*)d_out;

    const int smem_bytes = SMF * 4;
    cudaFuncSetAttribute(lmsc_kernel, cudaFuncAttributeMaxDynamicSharedMemorySize, smem_bytes);

    lmsc_kernel<<<NBLK, NTH, smem_bytes>>>(x, initF,
                                           w10, b10, w20, b20,
                                           w11, b11, w21, b21,
                                           w12, b12, w22, b22,
                                           wa, ba, wb, bb, wout, out);
}

// round 5
// speedup vs baseline: 1.2742x; 1.2480x over previous
#include <cuda_runtime.h>
#include <math.h>

typedef unsigned long long ull;

#define BATCH  1024
#define TSTEPS 1024
#define DIN    6
#define UNITS  64
#define WIDTH  128
#define DOUT   6
#define K0     70
#define EPSF   1e-8f
#define ROWS   8
#define NTH    256
#define NBLK   (BATCH / ROWS)

// ---------------- shared memory layout (float offsets) ----------------
// Weights: col-major, ODD stride (conflict-free LDS.32): W[j*stride + k]
// Acts: plain rowmajor-by-k: k*8 + r  (8 rows)
// STGO: L2 x1/x2 exchange m*1024 + p*256 + j*2 + e
//       then head partials  g*512 + p*128 + jh*2 + e
#define W10O  0                    // 128*71
#define W20O  9088
#define W11O  18176                // 128*129
#define W21O  34688
#define WOUTO 51200                // 384
#define BA    51584
#define BB    51648
#define C0P   51712                // 70*8 = 560   [x(6) | h(64)] plain
#define CBD   52272                // 128*8 = 1024
#define CB2   53296                // 1024
#define STGO  54320                // 2048
#define XB    56368                // 48
#define NB    56416                // 8
#define SMF   56424                // 225,696 bytes

__device__ __forceinline__ ull pack2(float lo, float hi) {
    ull r; asm("mov.b64 %0, {%1, %2};" : "=l"(r) : "f"(lo), "f"(hi)); return r;
}
__device__ __forceinline__ void unpack2(ull v, float& lo, float& hi) {
    asm("mov.b64 {%0, %1}, %2;" : "=f"(lo), "=f"(hi) : "l"(v));
}
__device__ __forceinline__ void ffma2(ull& d, ull a, ull b) {
    asm("fma.rn.f32x2 %0, %1, %2, %0;" : "+l"(d) : "l"(a), "l"(b));
}

// Fused both-mats layer. Acc packs (mat1,mat2) per row. Acts plain (1 bcast LDS.128/k),
// weights two conflict-free LDS.32/k. g[i] = tanh(x1)*tanh(x2), 4 rows.
template<int K, int UNR>
__device__ __forceinline__ void layer_fused(float (&g)[4], const float* __restrict__ actp,
                                            const float* __restrict__ wp1,
                                            const float* __restrict__ wp2, ull binit)
{
    ull a0 = binit, a1 = binit, a2 = binit, a3 = binit;
#pragma unroll UNR
    for (int k = 0; k < K; k++) {
        const float4 q = *(const float4*)(actp + k * 8);
        const ull w = pack2(wp1[k], wp2[k]);
        ffma2(a0, pack2(q.x, q.x), w);
        ffma2(a1, pack2(q.y, q.y), w);
        ffma2(a2, pack2(q.z, q.z), w);
        ffma2(a3, pack2(q.w, q.w), w);
    }
    float x1, x2;
    unpack2(a0, x1, x2); g[0] = tanhf(x1) * tanhf(x2);
    unpack2(a1, x1, x2); g[1] = tanhf(x1) * tanhf(x2);
    unpack2(a2, x1, x2); g[2] = tanhf(x1) * tanhf(x2);
    unpack2(a3, x1, x2); g[3] = tanhf(x1) * tanhf(x2);
}

__global__ void __launch_bounds__(NTH, 1)
lmsc_kernel(const float* __restrict__ x,   const float* __restrict__ initF,
            const float* __restrict__ w10, const float* __restrict__ b10,
            const float* __restrict__ w20, const float* __restrict__ b20,
            const float* __restrict__ w11, const float* __restrict__ b11,
            const float* __restrict__ w21, const float* __restrict__ b21,
            const float* __restrict__ w12, const float* __restrict__ b12,
            const float* __restrict__ w22, const float* __restrict__ b22,
            const float* __restrict__ wa,  const float* __restrict__ ba,
            const float* __restrict__ wb,  const float* __restrict__ bb,
            const float* __restrict__ wout, float* __restrict__ out)
{
    extern __shared__ float sm[];
    const int tid = threadIdx.x;
    const int b0  = blockIdx.x * ROWS;
    const int rh  = tid >> 7;        // row-half for fused layers; mat index for L2
    const int j   = tid & 127;       // column

    // ---- SMEM weight init (col-major, odd stride) ----
    for (int idx = tid; idx < K0 * WIDTH; idx += NTH) {
        int k = idx >> 7, jj = idx & 127;
        sm[W10O + jj * 71 + k] = w10[idx];
        sm[W20O + jj * 71 + k] = w20[idx];
    }
    for (int idx = tid; idx < WIDTH * WIDTH; idx += NTH) {
        int k = idx >> 7, jj = idx & 127;
        sm[W11O + jj * 129 + k] = w11[idx];
        sm[W21O + jj * 129 + k] = w21[idx];
    }
    for (int idx = tid; idx < UNITS * DOUT; idx += NTH) sm[WOUTO + idx] = wout[idx];
    if (tid < 64) { sm[BA + tid] = ba[tid]; sm[BB + tid] = bb[tid]; }
    // h0 plain
    for (int idx = tid; idx < ROWS * UNITS; idx += NTH) {
        int r = idx >> 6, jj = idx & 63;
        sm[C0P + (6 + jj) * 8 + r] = initF[(b0 + r) * (2 + UNITS) + 2 + jj];
    }

    // ---- per-thread register state ----
    const ull bp0 = pack2(b10[j], b20[j]);
    const ull bp1 = pack2(b11[j], b21[j]);
    const float bias2 = (rh ? b22 : b12)[j];

    float wl2[128];
    {
        const float* wsrc = rh ? w22 : w12;
#pragma unroll
        for (int k = 0; k < 128; k++) wl2[k] = wsrc[k * 128 + j];
    }
    const int hm = tid >> 7;
    const int kh = (tid >> 6) & 1;
    const int jh = tid & 63;
    float whd[64];
    {
        const float* hsrc = hm ? wb : wa;
#pragma unroll
        for (int i = 0; i < 64; i++) whd[i] = hsrc[(kh * 64 + i) * 64 + jh];
    }

    const float* actC0 = sm + C0P + rh * 4;
    const float* actCB = sm + CBD + rh * 4;
    const float* wp10  = sm + W10O + j * 71;
    const float* wp20  = sm + W20O + j * 71;
    const float* wp11  = sm + W11O + j * 129;
    const float* wp21  = sm + W21O + j * 129;

    // ---- x prologue: stage x(0), compute norm, prefetch x(1) ----
    const int xr = tid / 6, xd = tid - 6 * xr;
    float xc = 0.f;
    if (tid < 48) sm[XB + tid] = x[((size_t)(b0 + xr) * TSTEPS) * 6 + xd];
    __syncthreads();
    if (tid < 8) {
        float s = 0.f;
#pragma unroll
        for (int d = 0; d < 6; d++) { float v = sm[XB + tid * 6 + d]; s = fmaf(v, v, s); }
        float nrm = sqrtf(s);
        sm[NB + tid] = nrm;
        float inv = 1.0f / (nrm + EPSF);
#pragma unroll
        for (int d = 0; d < 6; d++) sm[C0P + d * 8 + tid] = sm[XB + tid * 6 + d] * inv;
    }
    if (tid < 48) xc = x[((size_t)(b0 + xr) * TSTEPS + 1) * 6 + xd];

    float* outs = out;
    float* alph = out + (size_t)BATCH * TSTEPS * DOUT;

#pragma unroll 1
    for (int t = 0; t < TSTEPS; t++) {
        __syncthreads();                                   // A: x/h/norm ready

        {   // layer 0 fused -> CBD (plain)
            float g[4];
            layer_fused<K0, 14>(g, actC0, wp10, wp20, bp0);
            *(float4*)(sm + CBD + j * 8 + rh * 4) = make_float4(g[0], g[1], g[2], g[3]);
        }
        __syncthreads();                                   // B

        {   // layer 1 fused -> CB2 (plain)
            float g[4];
            layer_fused<WIDTH, 16>(g, actCB, wp11, wp21, bp1);
            *(float4*)(sm + CB2 + j * 8 + rh * 4) = make_float4(g[0], g[1], g[2], g[3]);
        }
        __syncthreads();                                   // C

        {   // layer 2: split-mat, reg weights, rowpair acc -> STGO (m*1024 + p*256 + j*2)
            ull bp = pack2(bias2, bias2);
            ull a0 = bp, a1 = bp, a2 = bp, a3 = bp;
#pragma unroll
            for (int k = 0; k < 128; k++) {
                ulonglong2 u0 = *(const ulonglong2*)(sm + CB2 + k * 8);
                ulonglong2 u1 = *(const ulonglong2*)(sm + CB2 + k * 8 + 4);
                ull w = pack2(wl2[k], wl2[k]);
                ffma2(a0, u0.x, w); ffma2(a1, u0.y, w);
                ffma2(a2, u1.x, w); ffma2(a3, u1.y, w);
            }
            *(ull*)(sm + STGO + rh * 1024 + 0 * 256 + j * 2) = a0;
            *(ull*)(sm + STGO + rh * 1024 + 1 * 256 + j * 2) = a1;
            *(ull*)(sm + STGO + rh * 1024 + 2 * 256 + j * 2) = a2;
            *(ull*)(sm + STGO + rh * 1024 + 3 * 256 + j * 2) = a3;
        }
        __syncthreads();                                   // D

        // gate pass: CB2[j'*8 + p*2 + e] = tanh(x1 * x2)
#pragma unroll
        for (int it = 0; it < 4; it++) {
            int idx = it * 256 + tid;
            int jq  = idx >> 3;
            int rem = idx & 7;
            int src = ((rem >> 1) * 256) + jq * 2 + (rem & 1);
            float x1 = sm[STGO + src];
            float x2 = sm[STGO + 1024 + src];
            sm[CB2 + idx] = tanhf(x1 * x2);
        }
        __syncthreads();                                   // E

        {   // heads: split-K, reg weights -> compact partials g*512 + p*128 + jh*2 + e
            const float* actH = sm + CB2 + kh * 512;
            ull a0 = 0, a1 = 0, a2 = 0, a3 = 0;
#pragma unroll
            for (int i = 0; i < 64; i++) {
                ulonglong2 u0 = *(const ulonglong2*)(actH + i * 8);
                ulonglong2 u1 = *(const ulonglong2*)(actH + i * 8 + 4);
                ull w = pack2(whd[i], whd[i]);
                ffma2(a0, u0.x, w); ffma2(a1, u0.y, w);
                ffma2(a2, u1.x, w); ffma2(a3, u1.y, w);
            }
            const int g = hm * 2 + kh;
            *(ull*)(sm + STGO + g * 512 + 0 * 128 + jh * 2) = a0;
            *(ull*)(sm + STGO + g * 512 + 1 * 128 + jh * 2) = a1;
            *(ull*)(sm + STGO + g * 512 + 2 * 128 + jh * 2) = a2;
            *(ull*)(sm + STGO + g * 512 + 3 * 128 + jh * 2) = a3;
        }
        __syncthreads();                                   // F

        {   // combine: alpha/beta, h update, alpha out; also stage x(t+1)
            const int jj = tid & 63;
            const int rg = tid >> 6;
#pragma unroll
            for (int rr = 0; rr < 2; rr++) {
                const int r = rg * 2 + rr;
                float pa = sm[STGO + 0 * 512 + rg * 128 + jj * 2 + rr]
                         + sm[STGO + 1 * 512 + rg * 128 + jj * 2 + rr];
                float pb = sm[STGO + 2 * 512 + rg * 128 + jj * 2 + rr]
                         + sm[STGO + 3 * 512 + rg * 128 + jj * 2 + rr];
                float alpha = expf(pa + sm[BA + jj]);
                float beta  = tanhf(pb + sm[BB + jj]);
                float hold  = sm[C0P + (6 + jj) * 8 + r];
                float hn = fmaf(expf(-alpha * sm[NB + r]), hold - beta, beta);
                sm[C0P + (6 + jj) * 8 + r] = hn;
                alph[((size_t)(b0 + r) * TSTEPS + t) * 64 + jj] = alpha;
            }
            if (tid < 48 && t + 1 < TSTEPS) sm[XB + tid] = xc;
        }
        __syncthreads();                                   // G: h_new + x(t+1) staged

        if (tid < 48) {   // outs = h_new @ wout; also prefetch x(t+2)
            const int r = tid / 6, o = tid - 6 * r;
            float acc = 0.f;
#pragma unroll
            for (int k = 0; k < 64; k++)
                acc = fmaf(sm[C0P + (6 + k) * 8 + r], sm[WOUTO + k * 6 + o], acc);
            outs[((size_t)(b0 + r) * TSTEPS + t) * 6 + o] = acc;
            if (t + 2 < TSTEPS)
                xc = x[((size_t)(b0 + xr) * TSTEPS + (t + 2)) * 6 + xd];
        }
        if (tid < 8) {    // norm + xn for step t+1
            float s = 0.f;
#pragma unroll
            for (int d = 0; d < 6; d++) { float v = sm[XB + tid * 6 + d]; s = fmaf(v, v, s); }
            float nrm = sqrtf(s);
            sm[NB + tid] = nrm;
            float inv = 1.0f / (nrm + EPSF);
#pragma unroll
            for (int d = 0; d < 6; d++) sm[C0P + d * 8 + tid] = sm[XB + tid * 6 + d] * inv;
        }
    }
}

extern "C" void kernel_launch(void* const* d_in, const int* in_sizes, int n_in,
                              void* d_out, int out_size)
{
    const float* x     = (const float*)d_in[0];
    const float* initF = (const float*)d_in[1];
    const float* w10   = (const float*)d_in[2];
    const float* b10   = (const float*)d_in[3];
    const float* w20   = (const float*)d_in[4];
    const float* b20   = (const float*)d_in[5];
    const float* w11   = (const float*)d_in[6];
    const float* b11   = (const float*)d_in[7];
    const float* w21   = (const float*)d_in[8];
    const float* b21   = (const float*)d_in[9];
    const float* w12   = (const float*)d_in[10];
    const float* b12   = (const float*)d_in[11];
    const float* w22   = (const float*)d_in[12];
    const float* b22   = (const float*)d_in[13];
    const float* wa    = (const float*)d_in[14];
    const float* ba    = (const float*)d_in[15];
    const float* wb    = (const float*)d_in[16];
    const float* bb    = (const float*)d_in[17];
    const float* wout  = (const float*)d_in[18];
    float* out = (float*)d_out;

    const int smem_bytes = SMF * 4;
    cudaFuncSetAttribute(lmsc_kernel, cudaFuncAttributeMaxDynamicSharedMemorySize, smem_bytes);

    lmsc_kernel<<<NBLK, NTH, smem_bytes>>>(x, initF,
                                           w10, b10, w20, b20,
                                           w11, b11, w21, b21,
                                           w12, b12, w22, b22,
                                           wa, ba, wb, bb, wout, out);
}